// round 15
// baseline (speedup 1.0000x reference)
#include <cuda_runtime.h>
#include <cuda_fp16.h>
#include <cstring>
#include <cstdint>

#define N_SRC1 500000
#define N_DST1 100000
#define E1     1500000
#define N_DST2 20000
#define E2     200000
#define IN_F   128
#define H_F    256
#define N_CLS  47

#define NB1 98   // ceil(N_DST1/1024)
#define NB2 20   // ceil(N_DST2/1024)

// ---------------- scratch (device globals: no allocs allowed) ----------------
__device__ float g_hn1[(size_t)N_DST1 * IN_F];
__device__ float g_h[(size_t)N_DST1 * H_F];
__device__ float g_hn2[(size_t)N_DST2 * H_F];

__device__ __half g_W1[256 * 256];    // W1 fp16, [n][k]
__device__ __half g_W2[48 * 512];     // W2 fp16, [n][k] (row 47 = 0)

// zero-initialized at module load; re-zeroed by gemm2's tail every replay
__device__ int g_cnt1[N_DST1];
__device__ int g_cnt2[N_DST2];

__device__ int g_row1[N_DST1 + 1];
__device__ int g_cur1[N_DST1];
__device__ int g_eidx1[E1];

__device__ int g_row2[N_DST2 + 1];
__device__ int g_cur2[N_DST2];
__device__ int g_eidx2[E2];

__device__ int g_bsum1[128];
__device__ int g_bsum2[128];

// ---------------- helpers ----------------
__device__ __forceinline__ uint32_t sptr(const void* p) {
    return (uint32_t)__cvta_generic_to_shared(p);
}

// split 8 fp32 into fp16 hi/lo packs (A operand: ~22-bit accuracy)
__device__ __forceinline__ void split8h(float4 v0, float4 v1, uint4& hi, uint4& lo) {
    float f[8] = {v0.x, v0.y, v0.z, v0.w, v1.x, v1.y, v1.z, v1.w};
    __half h[8], l[8];
    #pragma unroll
    for (int i = 0; i < 8; i++) {
        h[i] = __float2half_rn(f[i]);
        l[i] = __float2half_rn(f[i] - __half2float(h[i]));
    }
    memcpy(&hi, h, 16);
    memcpy(&lo, l, 16);
}

__device__ __forceinline__ void ldm_x4(uint32_t* r, uint32_t addr) {
    asm volatile("ldmatrix.sync.aligned.m8n8.x4.shared.b16 {%0,%1,%2,%3}, [%4];"
                 : "=r"(r[0]), "=r"(r[1]), "=r"(r[2]), "=r"(r[3]) : "r"(addr));
}
__device__ __forceinline__ void ldm_x2(uint32_t* r, uint32_t addr) {
    asm volatile("ldmatrix.sync.aligned.m8n8.x2.shared.b16 {%0,%1}, [%2];"
                 : "=r"(r[0]), "=r"(r[1]) : "r"(addr));
}
__device__ __forceinline__ void mma16816(float* d, const uint32_t* a, uint32_t b0, uint32_t b1) {
    asm volatile(
        "mma.sync.aligned.m16n8k16.row.col.f32.f16.f16.f32 "
        "{%0,%1,%2,%3}, {%4,%5,%6,%7}, {%8,%9}, {%0,%1,%2,%3};"
        : "+f"(d[0]), "+f"(d[1]), "+f"(d[2]), "+f"(d[3])
        : "r"(a[0]), "r"(a[1]), "r"(a[2]), "r"(a[3]), "r"(b0), "r"(b1));
}

// ---------------- CSR counts (4 edges/thread) + W1/W2 fp16 transpose ----------------
__global__ void k_count_split(const int* __restrict__ d1, const int* __restrict__ d2,
                              const float* __restrict__ Ws1, const float* __restrict__ Wn1,
                              const float* __restrict__ Ws2, const float* __restrict__ Wn2) {
    int gid = blockIdx.x * blockDim.x + threadIdx.x;
    if (gid < 256 * 256) {   // W1: [k][n] fp32 -> [n][k] fp16
        int k = gid >> 8;
        int n = gid & 255;
        float w = (k < 128) ? Ws1[k * 256 + n] : Wn1[(k - 128) * 256 + n];
        g_W1[n * 256 + k] = __float2half_rn(w);
    }
    if (gid < 48 * 512) {    // W2: [k][47] fp32 -> [48][512] fp16 (row 47 = 0)
        int n = gid >> 9;
        int k = gid & 511;
        float w = 0.f;
        if (n < N_CLS) w = (k < 256) ? Ws2[k * N_CLS + n] : Wn2[(k - 256) * N_CLS + n];
        g_W2[n * 512 + k] = __float2half_rn(w);
    }
    int i4 = gid * 4;
    if (i4 < E1) {           // E1 % 4 == 0
        int4 d = *(const int4*)(d1 + i4);
        atomicAdd(&g_cnt1[d.x], 1);
        atomicAdd(&g_cnt1[d.y], 1);
        atomicAdd(&g_cnt1[d.z], 1);
        atomicAdd(&g_cnt1[d.w], 1);
    }
    if (i4 < E2) {           // E2 % 4 == 0
        int4 d = *(const int4*)(d2 + i4);
        atomicAdd(&g_cnt2[d.x], 1);
        atomicAdd(&g_cnt2[d.y], 1);
        atomicAdd(&g_cnt2[d.z], 1);
        atomicAdd(&g_cnt2[d.w], 1);
    }
}

__global__ void k_scanA() {
    __shared__ int s[1024];
    int b = blockIdx.x;
    const int* cnt; int n; int* bsum; int bb;
    if (b < NB1) { cnt = g_cnt1; n = N_DST1; bsum = g_bsum1; bb = b; }
    else         { cnt = g_cnt2; n = N_DST2; bsum = g_bsum2; bb = b - NB1; }
    int i = bb * 1024 + threadIdx.x;
    int v = (i < n) ? cnt[i] : 0;
    s[threadIdx.x] = v;
    __syncthreads();
    #pragma unroll
    for (int off = 512; off > 0; off >>= 1) {
        if (threadIdx.x < off) s[threadIdx.x] += s[threadIdx.x + off];
        __syncthreads();
    }
    if (threadIdx.x == 0) bsum[bb] = s[0];
}

// scanC with scanB folded in: each block re-scans the (<=128) block sums locally.
__global__ void k_scanC() {
    __shared__ int s[1024];
    __shared__ int sbs[128];
    int b = blockIdx.x;
    const int* cnt; int n; int* row; int* cur; int bb; int etot; const int* bsum; int nb;
    if (b < NB1) { cnt = g_cnt1; n = N_DST1; row = g_row1; cur = g_cur1; bb = b;       etot = E1; bsum = g_bsum1; nb = NB1; }
    else         { cnt = g_cnt2; n = N_DST2; row = g_row2; cur = g_cur2; bb = b - NB1; etot = E2; bsum = g_bsum2; nb = NB2; }
    int t = threadIdx.x;

    if (t < 128) sbs[t] = (t < nb) ? bsum[t] : 0;
    __syncthreads();
    #pragma unroll
    for (int off = 1; off < 128; off <<= 1) {
        int v = 0;
        if (t < 128 && t >= off) v = sbs[t - off];
        __syncthreads();
        if (t < 128) sbs[t] += v;
        __syncthreads();
    }
    int boff = (bb > 0) ? sbs[bb - 1] : 0;

    int i = bb * 1024 + t;
    int v = (i < n) ? cnt[i] : 0;
    s[t] = v;
    __syncthreads();
    #pragma unroll
    for (int off = 1; off < 1024; off <<= 1) {
        int u = (t >= off) ? s[t - off] : 0;
        __syncthreads();
        s[t] += u;
        __syncthreads();
    }
    int excl = boff + s[t] - v;
    if (i < n) { row[i] = excl; cur[i] = excl; }
    if (i == n - 1) row[n] = etot;
}

// fill: 4 edges/thread, vector loads, 4 independent atomic chains
__global__ void k_fill(const int* __restrict__ s1, const int* __restrict__ d1,
                       const int* __restrict__ s2, const int* __restrict__ d2) {
    int gid = blockIdx.x * blockDim.x + threadIdx.x;
    int i4 = gid * 4;
    if (i4 < E1) {
        int4 d = *(const int4*)(d1 + i4);
        int4 s = *(const int4*)(s1 + i4);
        int p0 = atomicAdd(&g_cur1[d.x], 1);
        int p1 = atomicAdd(&g_cur1[d.y], 1);
        int p2 = atomicAdd(&g_cur1[d.z], 1);
        int p3 = atomicAdd(&g_cur1[d.w], 1);
        g_eidx1[p0] = s.x;
        g_eidx1[p1] = s.y;
        g_eidx1[p2] = s.z;
        g_eidx1[p3] = s.w;
    }
    if (i4 < E2) {
        int4 d = *(const int4*)(d2 + i4);
        int4 s = *(const int4*)(s2 + i4);
        int p0 = atomicAdd(&g_cur2[d.x], 1);
        int p1 = atomicAdd(&g_cur2[d.y], 1);
        int p2 = atomicAdd(&g_cur2[d.z], 1);
        int p3 = atomicAdd(&g_cur2[d.w], 1);
        g_eidx2[p0] = s.x;
        g_eidx2[p1] = s.y;
        g_eidx2[p2] = s.z;
        g_eidx2[p3] = s.w;
    }
}

// ---------------- aggregation (warp per dst node, deep unroll for MLP) ----------------
__global__ void k_agg1(const float4* __restrict__ x4) {
    int w = (blockIdx.x * blockDim.x + threadIdx.x) >> 5;
    int lane = threadIdx.x & 31;
    if (w >= N_DST1) return;
    int e0 = g_row1[w], e1 = g_row1[w + 1];
    float4 acc = make_float4(0.f, 0.f, 0.f, 0.f);
    int e = e0;
    for (; e + 7 < e1; e += 8) {
        int si[8];
        #pragma unroll
        for (int j = 0; j < 8; j++) si[j] = g_eidx1[e + j];
        float4 v[8];
        #pragma unroll
        for (int j = 0; j < 8; j++) v[j] = __ldg(&x4[(size_t)si[j] * 32 + lane]);
        #pragma unroll
        for (int j = 0; j < 8; j++) {
            acc.x += v[j].x; acc.y += v[j].y; acc.z += v[j].z; acc.w += v[j].w;
        }
    }
    for (; e + 3 < e1; e += 4) {
        int si[4];
        #pragma unroll
        for (int j = 0; j < 4; j++) si[j] = g_eidx1[e + j];
        float4 v[4];
        #pragma unroll
        for (int j = 0; j < 4; j++) v[j] = __ldg(&x4[(size_t)si[j] * 32 + lane]);
        #pragma unroll
        for (int j = 0; j < 4; j++) {
            acc.x += v[j].x; acc.y += v[j].y; acc.z += v[j].z; acc.w += v[j].w;
        }
    }
    for (; e < e1; e++) {
        int sa = g_eidx1[e];
        float4 va = __ldg(&x4[(size_t)sa * 32 + lane]);
        acc.x += va.x; acc.y += va.y; acc.z += va.z; acc.w += va.w;
    }
    float inv = 1.0f / fmaxf((float)(e1 - e0), 1.0f);
    acc.x *= inv; acc.y *= inv; acc.z *= inv; acc.w *= inv;
    ((float4*)g_hn1)[(size_t)w * 32 + lane] = acc;
}

__global__ void k_agg2() {
    int w = (blockIdx.x * blockDim.x + threadIdx.x) >> 5;
    int lane = threadIdx.x & 31;
    if (w >= N_DST2) return;
    const float4* h4 = (const float4*)g_h;
    int e0 = g_row2[w], e1 = g_row2[w + 1];
    float4 a0 = make_float4(0.f, 0.f, 0.f, 0.f);
    float4 a1 = make_float4(0.f, 0.f, 0.f, 0.f);
    int e = e0;
    for (; e + 1 < e1; e += 2) {
        int sa = g_eidx2[e];
        int sb = g_eidx2[e + 1];
        float4 va0 = __ldg(&h4[(size_t)sa * 64 + lane]);
        float4 va1 = __ldg(&h4[(size_t)sa * 64 + lane + 32]);
        float4 vb0 = __ldg(&h4[(size_t)sb * 64 + lane]);
        float4 vb1 = __ldg(&h4[(size_t)sb * 64 + lane + 32]);
        a0.x += va0.x + vb0.x; a0.y += va0.y + vb0.y;
        a0.z += va0.z + vb0.z; a0.w += va0.w + vb0.w;
        a1.x += va1.x + vb1.x; a1.y += va1.y + vb1.y;
        a1.z += va1.z + vb1.z; a1.w += va1.w + vb1.w;
    }
    for (; e < e1; e++) {
        int s = g_eidx2[e];
        float4 v0 = __ldg(&h4[(size_t)s * 64 + lane]);
        float4 v1 = __ldg(&h4[(size_t)s * 64 + lane + 32]);
        a0.x += v0.x; a0.y += v0.y; a0.z += v0.z; a0.w += v0.w;
        a1.x += v1.x; a1.y += v1.y; a1.z += v1.z; a1.w += v1.w;
    }
    float inv = 1.0f / fmaxf((float)(e1 - e0), 1.0f);
    a0.x *= inv; a0.y *= inv; a0.z *= inv; a0.w *= inv;
    a1.x *= inv; a1.y *= inv; a1.z *= inv; a1.w *= inv;
    ((float4*)g_hn2)[(size_t)w * 64 + lane] = a0;
    ((float4*)g_hn2)[(size_t)w * 64 + lane + 32] = a1;
}

// ---------------- layer-1 GEMM (HMMA fp16 2-pass, K-chunk 32) ----------------
#define AP1 40      // fp16 elems per smem row for gemm1 (32 data + 8 pad = 80B)
#define APITCH 24   // fp16 elems per smem row for gemm2 (16 data + 8 pad = 48B)

__global__ __launch_bounds__(256, 2) void k_gemm1(const float* __restrict__ x,
                                                  const float* __restrict__ b1) {
    __shared__ __half sAhi[128 * AP1];
    __shared__ __half sAlo[128 * AP1];
    __shared__ __half sB[128 * AP1];

    int t = threadIdx.x;
    int lane = t & 31;
    int wid = t >> 5;
    int m0 = blockIdx.y * 128;
    int n0 = blockIdx.x * 128;
    int wm = (wid & 3) * 32;
    int wn = (wid >> 2) * 64;

    float acc[2][8][4];
    #pragma unroll
    for (int i = 0; i < 2; i++)
        #pragma unroll
        for (int j = 0; j < 8; j++)
            #pragma unroll
            for (int q = 0; q < 4; q++) acc[i][j][q] = 0.f;

    int lrow = t >> 1;            // 0..127
    int lq   = (t & 1) << 4;      // 0 or 16 (each thread: 16 elems)
    int grow = m0 + lrow;

    uint32_t aHi = sptr(sAhi), aLo = sptr(sAlo), bB = sptr(sB);
    int a_r = (lane & 15);
    int a_c = (lane >> 4) << 3;
    int b_r = (lane & 7) + ((lane >> 4) << 3);
    int b_c = ((lane >> 3) & 1) << 3;

    float4 pA[4];
    uint4 pB[2];

    auto ldA = [&](int kc) {   // kc 0..7, 32 fp32 each; 0-3 from x, 4-7 from hn1
        const float* Ab = (kc < 4) ? (x + kc * 32) : (g_hn1 + (kc - 4) * 32);
        if (grow < N_DST1) {
            const float* p = Ab + (size_t)grow * IN_F + lq;
            pA[0] = *(const float4*)p;
            pA[1] = *(const float4*)(p + 4);
            pA[2] = *(const float4*)(p + 8);
            pA[3] = *(const float4*)(p + 12);
        } else {
            pA[0] = pA[1] = pA[2] = pA[3] = make_float4(0.f, 0.f, 0.f, 0.f);
        }
    };
    auto ldB = [&](int kc) {
        const __half* p = g_W1 + (size_t)(n0 + lrow) * 256 + kc * 32 + lq;
        pB[0] = *(const uint4*)p;
        pB[1] = *(const uint4*)(p + 8);
    };
    auto sts = [&]() {
        uint4 hi0, lo0, hi1, lo1;
        split8h(pA[0], pA[1], hi0, lo0);
        split8h(pA[2], pA[3], hi1, lo1);
        *(uint4*)&sAhi[lrow * AP1 + lq] = hi0;
        *(uint4*)&sAhi[lrow * AP1 + lq + 8] = hi1;
        *(uint4*)&sAlo[lrow * AP1 + lq] = lo0;
        *(uint4*)&sAlo[lrow * AP1 + lq + 8] = lo1;
        *(uint4*)&sB[lrow * AP1 + lq] = pB[0];
        *(uint4*)&sB[lrow * AP1 + lq + 8] = pB[1];
    };
    auto fused = [&](int ks) {   // ks = 0 or 16 within the 32-wide chunk
        uint32_t ah[2][4], al[2][4];
        #pragma unroll
        for (int mf = 0; mf < 2; mf++) {
            uint32_t ao = ((wm + mf * 16 + a_r) * AP1 + ks + a_c) * 2;
            ldm_x4(ah[mf], aHi + ao);
            ldm_x4(al[mf], aLo + ao);
        }
        #pragma unroll
        for (int pair = 0; pair < 4; pair++) {
            uint32_t bb[4];
            ldm_x4(bb, bB + ((wn + pair * 16 + b_r) * AP1 + ks + b_c) * 2);
            #pragma unroll
            for (int mf = 0; mf < 2; mf++) {
                float* d0 = acc[mf][pair * 2];
                float* d1 = acc[mf][pair * 2 + 1];
                mma16816(d0, ah[mf], bb[0], bb[1]);
                mma16816(d1, ah[mf], bb[2], bb[3]);
                mma16816(d0, al[mf], bb[0], bb[1]);
                mma16816(d1, al[mf], bb[2], bb[3]);
            }
        }
    };

    ldA(0);
    ldB(0);
    for (int kc = 0; kc < 8; kc++) {
        sts();
        __syncthreads();
        if (kc < 7) { ldA(kc + 1); ldB(kc + 1); }
        fused(0);
        fused(16);
        __syncthreads();
    }

    #pragma unroll
    for (int mf = 0; mf < 2; mf++) {
        int gr0 = m0 + wm + mf * 16 + (lane >> 2);
        int gr1 = gr0 + 8;
        #pragma unroll
        for (int nf = 0; nf < 8; nf++) {
            int gn = n0 + wn + nf * 8 + ((lane & 3) << 1);
            float bx = b1[gn];
            float by = b1[gn + 1];
            float* d = acc[mf][nf];
            if (gr0 < N_DST1)
                *(float2*)&g_h[(size_t)gr0 * H_F + gn] =
                    make_float2(fmaxf(d[0] + bx, 0.f), fmaxf(d[1] + by, 0.f));
            if (gr1 < N_DST1)
                *(float2*)&g_h[(size_t)gr1 * H_F + gn] =
                    make_float2(fmaxf(d[2] + bx, 0.f), fmaxf(d[3] + by, 0.f));
        }
    }
}

// ---------------- layer-2 GEMM (HMMA fp16 2-pass) + count-rezero tail ----------------
__global__ __launch_bounds__(256, 2) void k_gemm2(const float* __restrict__ b2,
                                                  float* __restrict__ out) {
    __shared__ __half sAhi[128 * APITCH];
    __shared__ __half sAlo[128 * APITCH];
    __shared__ __half sB[48 * APITCH];

    int t = threadIdx.x;
    int lane = t & 31;
    int wid = t >> 5;
    int m0 = blockIdx.x * 128;
    int wm = (wid & 3) * 32;
    int wn = (wid >> 2) * 24;

    float acc[2][3][4];
    #pragma unroll
    for (int i = 0; i < 2; i++)
        #pragma unroll
        for (int j = 0; j < 3; j++)
            #pragma unroll
            for (int q = 0; q < 4; q++) acc[i][j][q] = 0.f;

    int lrow = t >> 1;
    int lq   = (t & 1) << 3;
    int grow = m0 + lrow;

    uint32_t aHi = sptr(sAhi), aLo = sptr(sAlo), bB = sptr(sB);
    int a_r = (lane & 15);
    int a_c = (lane >> 4) << 3;
    int b_r = (lane & 7) + ((lane >> 4) << 3);
    int b_c = ((lane >> 3) & 1) << 3;
    int b2_r = lane & 7;
    int b2_c = ((lane >> 3) & 1) << 3;

    float4 pA0, pA1;
    uint4 pB;

    auto ldA = [&](int kc) {
        const float* Ab = (kc < 16) ? (g_h + kc * 16) : (g_hn2 + (kc - 16) * 16);
        if (grow < N_DST2) {
            const float* p = Ab + (size_t)grow * H_F + lq;
            pA0 = *(const float4*)p;
            pA1 = *(const float4*)(p + 4);
        } else {
            pA0 = make_float4(0.f, 0.f, 0.f, 0.f);
            pA1 = make_float4(0.f, 0.f, 0.f, 0.f);
        }
    };
    auto ldB = [&](int kc) {
        if (t < 96) {
            int row = t >> 1;
            int half = (t & 1) << 3;
            pB = *(const uint4*)(g_W2 + (size_t)row * 512 + kc * 16 + half);
        }
    };
    auto sts = [&]() {
        uint4 hi, lo;
        split8h(pA0, pA1, hi, lo);
        *(uint4*)&sAhi[lrow * APITCH + lq] = hi;
        *(uint4*)&sAlo[lrow * APITCH + lq] = lo;
        if (t < 96) {
            int row = t >> 1;
            int half = (t & 1) << 3;
            *(uint4*)&sB[row * APITCH + half] = pB;
        }
    };
    auto fused = [&]() {
        uint32_t ah[2][4], al[2][4];
        #pragma unroll
        for (int mf = 0; mf < 2; mf++) {
            uint32_t ao = ((wm + mf * 16 + a_r) * APITCH + a_c) * 2;
            ldm_x4(ah[mf], aHi + ao);
            ldm_x4(al[mf], aLo + ao);
        }
        uint32_t b4[4], bx2[2];
        ldm_x4(b4, bB + ((wn + b_r) * APITCH + b_c) * 2);
        ldm_x2(bx2, bB + ((wn + 16 + b2_r) * APITCH + b2_c) * 2);
        #pragma unroll
        for (int mf = 0; mf < 2; mf++) {
            mma16816(acc[mf][0], ah[mf], b4[0], b4[1]);
            mma16816(acc[mf][1], ah[mf], b4[2], b4[3]);
            mma16816(acc[mf][2], ah[mf], bx2[0], bx2[1]);
            mma16816(acc[mf][0], al[mf], b4[0], b4[1]);
            mma16816(acc[mf][1], al[mf], b4[2], b4[3]);
            mma16816(acc[mf][2], al[mf], bx2[0], bx2[1]);
        }
    };

    ldA(0);
    ldB(0);
    for (int kc = 0; kc < 32; kc++) {
        sts();
        __syncthreads();
        if (kc < 31) { ldA(kc + 1); ldB(kc + 1); }
        fused();
        __syncthreads();
    }

    #pragma unroll
    for (int mf = 0; mf < 2; mf++) {
        int gr0 = m0 + wm + mf * 16 + (lane >> 2);
        int gr1 = gr0 + 8;
        #pragma unroll
        for (int nf = 0; nf < 3; nf++) {
            int gn = wn + nf * 8 + ((lane & 3) << 1);
            float* d = acc[mf][nf];
            if (gn < N_CLS) {
                float bx = b2[gn];
                if (gr0 < N_DST2) out[(size_t)gr0 * N_CLS + gn] = d[0] + bx;
                if (gr1 < N_DST2) out[(size_t)gr1 * N_CLS + gn] = d[2] + bx;
            }
            if (gn + 1 < N_CLS) {
                float by = b2[gn + 1];
                if (gr0 < N_DST2) out[(size_t)gr0 * N_CLS + gn + 1] = d[1] + by;
                if (gr1 < N_DST2) out[(size_t)gr1 * N_CLS + gn + 1] = d[3] + by;
            }
        }
    }

    // rezero counts for the next graph replay (grid-stride)
    int stride = gridDim.x * blockDim.x;
    for (int i = blockIdx.x * blockDim.x + t; i < N_DST1; i += stride) g_cnt1[i] = 0;
    for (int i = blockIdx.x * blockDim.x + t; i < N_DST2; i += stride) g_cnt2[i] = 0;
}

// ---------------- launch ----------------
extern "C" void kernel_launch(void* const* d_in, const int* in_sizes, int n_in,
                              void* d_out, int out_size) {
    const float* x   = (const float*)d_in[0];
    const float* Ws1 = (const float*)d_in[1];
    const float* Wn1 = (const float*)d_in[2];
    const float* b1  = (const float*)d_in[3];
    const float* Ws2 = (const float*)d_in[4];
    const float* Wn2 = (const float*)d_in[5];
    const float* b2  = (const float*)d_in[6];
    const int* src1  = (const int*)d_in[7];
    const int* dst1  = (const int*)d_in[8];
    const int* src2  = (const int*)d_in[9];
    const int* dst2  = (const int*)d_in[10];
    float* out = (float*)d_out;

    int qblk = (E1 / 4 + 255) / 256;   // 1465 blocks = 375,040 threads (>= 65,536 for W-split)
    k_count_split<<<qblk, 256>>>(dst1, dst2, Ws1, Wn1, Ws2, Wn2);     // 0
    k_scanA<<<NB1 + NB2, 1024>>>();                                   // 1
    k_scanC<<<NB1 + NB2, 1024>>>();                                   // 2 (scanB folded in)
    k_fill<<<qblk, 256>>>(src1, dst1, src2, dst2);                    // 3
    k_agg1<<<(N_DST1 * 32 + 255) / 256, 256>>>((const float4*)x);     // 4
    dim3 g1(2, (N_DST1 + 127) / 128);
    k_gemm1<<<g1, 256>>>(x, b1);                                      // 5
    k_agg2<<<(N_DST2 * 32 + 255) / 256, 256>>>();                     // 6
    k_gemm2<<<(N_DST2 + 127) / 128, 256>>>(b2, out);                  // 7
}